// round 1
// baseline (speedup 1.0000x reference)
#include <cuda_runtime.h>
#include <cstdint>

#define D_IN     4096
#define R_RANK   16
#define O_OUT    4096
#define SCALING  2.0f      // alpha/rank = 32/16
#define DC       512       // d-chunk size (floats) and o-chunk size (rows)
#define STRIDE   20        // smem row stride in floats (bank-conflict-free @ LDS.128)
#define TOK_PER_CTA 32
#define THREADS  256

// ---- packed f32x2 helpers (ptxas will not auto-fuse FFMA2 from C++) ----
__device__ __forceinline__ unsigned long long pack2(float a, float b) {
    unsigned long long r;
    asm("mov.b64 %0, {%1, %2};" : "=l"(r) : "f"(a), "f"(b));
    return r;
}
__device__ __forceinline__ void unpack2(unsigned long long v, float &a, float &b) {
    asm("mov.b64 {%0, %1}, %2;" : "=f"(a), "=f"(b) : "l"(v));
}
__device__ __forceinline__ unsigned long long fma2(unsigned long long a,
                                                   unsigned long long b,
                                                   unsigned long long c) {
    unsigned long long d;
    asm("fma.rn.f32x2 %0, %1, %2, %3;" : "=l"(d) : "l"(a), "l"(b), "l"(c));
    return d;
}

// Fused LoRA: per CTA, 8 warps x 4 tokens. Phase 1 computes h = (x A^T) * s into
// smem; phase 2 computes out = h B^T. A and B are streamed through one shared
// 40KB staging buffer.
__global__ void __launch_bounds__(THREADS, 2)
lora_fused(const float* __restrict__ x, const float* __restrict__ A,
           const float* __restrict__ B, float* __restrict__ out) {
    __shared__ float buf[DC * STRIDE];   // 40 KB: A^T chunk, then B chunk
    __shared__ float h_s[8 * 64];        // per-warp: 4 tokens x 16 r

    const int tid  = threadIdx.x;
    const int lane = tid & 31;
    const int warp = tid >> 5;
    const int m0   = blockIdx.x * TOK_PER_CTA + warp * 4;

    // ================= phase 1: h = x @ A^T =================
    unsigned long long acc2[4][8];
    #pragma unroll
    for (int t = 0; t < 4; ++t)
        #pragma unroll
        for (int p = 0; p < 8; ++p) acc2[t][p] = 0ull;

    const float* x0 = x + (size_t)(m0 + 0) * D_IN;
    const float* x1 = x + (size_t)(m0 + 1) * D_IN;
    const float* x2 = x + (size_t)(m0 + 2) * D_IN;
    const float* x3 = x + (size_t)(m0 + 3) * D_IN;

    for (int dc = 0; dc < D_IN; dc += DC) {
        // Stage A chunk transposed: buf[dl*STRIDE + r] = A[r][dc+dl].
        // Global reads coalesced (dl contiguous per warp); smem stores are
        // (20*lane + r) mod 32 -> at most 4-way.
        #pragma unroll
        for (int i = 0; i < (DC * R_RANK) / THREADS; ++i) {   // 32 iters
            int idx = tid + i * THREADS;          // 0 .. 8191
            int r   = idx >> 9;                   // idx / DC
            int dl  = idx & (DC - 1);
            buf[dl * STRIDE + r] = A[r * D_IN + dc + dl];
        }
        __syncthreads();

        // Lanes split d; each lane: 1 d per iter, 4 tokens, 16 r -> 32 FFMA2.
        #pragma unroll 4
        for (int j = 0; j < DC / 32; ++j) {
            int dl = j * 32 + lane;
            int d  = dc + dl;
            float xv0 = x0[d], xv1 = x1[d], xv2 = x2[d], xv3 = x3[d];
            const ulonglong2* ap =
                reinterpret_cast<const ulonglong2*>(buf + dl * STRIDE);
            ulonglong2 q0 = ap[0], q1 = ap[1], q2 = ap[2], q3 = ap[3];
            unsigned long long a2[8] = {q0.x, q0.y, q1.x, q1.y,
                                        q2.x, q2.y, q3.x, q3.y};
            unsigned long long xx0 = pack2(xv0, xv0);
            unsigned long long xx1 = pack2(xv1, xv1);
            unsigned long long xx2 = pack2(xv2, xv2);
            unsigned long long xx3 = pack2(xv3, xv3);
            #pragma unroll
            for (int p = 0; p < 8; ++p) {
                acc2[0][p] = fma2(xx0, a2[p], acc2[0][p]);
                acc2[1][p] = fma2(xx1, a2[p], acc2[1][p]);
                acc2[2][p] = fma2(xx2, a2[p], acc2[2][p]);
                acc2[3][p] = fma2(xx3, a2[p], acc2[3][p]);
            }
        }
        __syncthreads();
    }

    // Unpack and reduce the d-split partials across the warp.
    float acc[4][16];
    #pragma unroll
    for (int t = 0; t < 4; ++t)
        #pragma unroll
        for (int p = 0; p < 8; ++p)
            unpack2(acc2[t][p], acc[t][2 * p], acc[t][2 * p + 1]);

    #pragma unroll
    for (int off = 16; off > 0; off >>= 1)
        #pragma unroll
        for (int t = 0; t < 4; ++t)
            #pragma unroll
            for (int r = 0; r < R_RANK; ++r)
                acc[t][r] += __shfl_xor_sync(0xffffffffu, acc[t][r], off);

    // Each lane owns 2 of the 64 (t,r) results; static selection, no spills.
    float v0 = 0.f, v1 = 0.f;
    #pragma unroll
    for (int t = 0; t < 4; ++t)
        #pragma unroll
        for (int r = 0; r < R_RANK; ++r) {
            int idx = t * 16 + r;
            if (idx < 32) { if (lane == idx)      v0 = acc[t][r]; }
            else          { if (lane == idx - 32) v1 = acc[t][r]; }
        }
    h_s[warp * 64 + lane]      = v0 * SCALING;   // tokens m0, m0+1
    h_s[warp * 64 + 32 + lane] = v1 * SCALING;   // tokens m0+2, m0+3

    __syncthreads();   // h_s ready; buf free for B

    // ================= phase 2: out = h @ B^T =================
    // Load this warp's h as packed r-pairs (smem broadcast, conflict-free).
    unsigned long long h2[4][8];
    #pragma unroll
    for (int t = 0; t < 4; ++t) {
        const ulonglong2* hp =
            reinterpret_cast<const ulonglong2*>(h_s + warp * 64 + t * 16);
        ulonglong2 u0 = hp[0], u1 = hp[1], u2 = hp[2], u3 = hp[3];
        h2[t][0] = u0.x; h2[t][1] = u0.y; h2[t][2] = u1.x; h2[t][3] = u1.y;
        h2[t][4] = u2.x; h2[t][5] = u2.y; h2[t][6] = u3.x; h2[t][7] = u3.y;
    }

    float* o0 = out + (size_t)(m0 + 0) * O_OUT;
    float* o1 = out + (size_t)(m0 + 1) * O_OUT;
    float* o2 = out + (size_t)(m0 + 2) * O_OUT;
    float* o3 = out + (size_t)(m0 + 3) * O_OUT;

    for (int oc = 0; oc < O_OUT; oc += DC) {
        // Stage B chunk: buf[ol*STRIDE + r] = B[(oc+ol)*16 + r], float4 copies.
        #pragma unroll
        for (int i = 0; i < (DC * R_RANK) / (THREADS * 4); ++i) {  // 8 iters
            int f4 = tid + i * THREADS;       // float4 index, 0..2047
            int ol = f4 >> 2;
            int c  = f4 & 3;
            float4 v = reinterpret_cast<const float4*>(B + (oc + ol) * R_RANK)[c];
            *reinterpret_cast<float4*>(buf + ol * STRIDE + c * 4) = v;
        }
        __syncthreads();

        // Lane owns one o per iter; FFMA2 over r-pairs (even/odd partials),
        // one horizontal add at the end. Stores coalesced STG.32.
        #pragma unroll 4
        for (int og = 0; og < DC; og += 32) {
            int ol = og + lane;
            const ulonglong2* bp =
                reinterpret_cast<const ulonglong2*>(buf + ol * STRIDE);
            ulonglong2 q0 = bp[0], q1 = bp[1], q2 = bp[2], q3 = bp[3];
            unsigned long long b2[8] = {q0.x, q0.y, q1.x, q1.y,
                                        q2.x, q2.y, q3.x, q3.y};
            unsigned long long s0 = 0ull, s1 = 0ull, s2 = 0ull, s3 = 0ull;
            #pragma unroll
            for (int p = 0; p < 8; ++p) {
                s0 = fma2(h2[0][p], b2[p], s0);
                s1 = fma2(h2[1][p], b2[p], s1);
                s2 = fma2(h2[2][p], b2[p], s2);
                s3 = fma2(h2[3][p], b2[p], s3);
            }
            int o = oc + ol;
            float lo, hi;
            unpack2(s0, lo, hi); o0[o] = lo + hi;
            unpack2(s1, lo, hi); o1[o] = lo + hi;
            unpack2(s2, lo, hi); o2[o] = lo + hi;
            unpack2(s3, lo, hi); o3[o] = lo + hi;
        }
        __syncthreads();
    }
}

extern "C" void kernel_launch(void* const* d_in, const int* in_sizes, int n_in,
                              void* d_out, int out_size) {
    const float* x = (const float*)d_in[0];
    const float* A = (const float*)d_in[1];   // [16, 4096]
    const float* B = (const float*)d_in[2];   // [4096, 16]
    float* out = (float*)d_out;

    int m_total = in_sizes[0] / D_IN;         // 8192 tokens
    int blocks  = m_total / TOK_PER_CTA;      // 256 CTAs
    lora_fused<<<blocks, THREADS>>>(x, A, B, out);
}